// round 8
// baseline (speedup 1.0000x reference)
#include <cuda_runtime.h>
#include <math.h>
#include <stdint.h>

// ---------------- problem constants ----------------
#define L_    2
#define D_    256
#define DFF_  1024
#define NH_   8
#define NP_   4
#define CIN_  512
#define B_    8
#define HH_   64
#define WW_   64
#define HW_   4096
#define EPS_  1e-5f

// ---------------- GEMM tiling ----------------
#define BM 128
#define BN 128
#define BK 16

// ---------------- scratch (device globals; allocation-free) ----------------
__device__ __align__(128) float g_src   [B_*HW_*D_];
__device__ __align__(128) float g_q     [B_*HW_*D_];
__device__ __align__(128) float g_val   [B_*HW_*D_];
__device__ __align__(128) float g_samp  [B_*HW_*D_];
__device__ __align__(128) float g_tmp   [B_*HW_*D_];
__device__ __align__(128) float g_ffn   [B_*HW_*DFF_];
__device__ __align__(128) float g_loc   [B_*HW_*NH_*NP_*2];
__device__ __align__(128) float g_attw  [B_*HW_*NH_*NP_];
__device__ __align__(128) float g_logits[B_*HW_*128];
__device__ __align__(128) float g_wcat  [L_*D_*128];
__device__ __align__(128) float g_bcat  [L_*128];
// pre-rounded (tf32) weights
__device__ __align__(128) float g_rw    [1572864];

// offsets into g_rw
#define OW_IN   0
#define OW_VAL  131072
#define OW_O    262144
#define OW_1    393216
#define OW_2    917504
#define OW_OUT  1441792

// ---------------- small helpers ----------------
__device__ __forceinline__ void cp16(float* dst, const float* src) {
    uint32_t d = (uint32_t)__cvta_generic_to_shared(dst);
    asm volatile("cp.async.cg.shared.global [%0], [%1], 16;\n" :: "r"(d), "l"(src));
}
__device__ __forceinline__ uint32_t f2tf(float f) {
    uint32_t u; asm("cvt.rna.tf32.f32 %0, %1;" : "=r"(u) : "f"(f)); return u;
}
__device__ __forceinline__ float f2tff(float f) {
    return __uint_as_float(f2tf(f));
}
__device__ __forceinline__ void mma8(float* c, const uint32_t* a, const uint32_t* b) {
    asm volatile(
        "mma.sync.aligned.m16n8k8.row.col.f32.tf32.tf32.f32 "
        "{%0,%1,%2,%3},{%4,%5,%6,%7},{%8,%9},{%0,%1,%2,%3};"
        : "+f"(c[0]), "+f"(c[1]), "+f"(c[2]), "+f"(c[3])
        : "r"(a[0]), "r"(a[1]), "r"(a[2]), "r"(a[3]), "r"(b[0]), "r"(b[1]));
}

// ============================================================
// TF32 tensor-core GEMM.  C[M,N] = op(A) @ op(B) + epilogue
//  AMODE 0: A row-major [M,K]; AMODE 1: A k-major A[k][m]
//  BMODE 0: B row-major [K,N] (cp.async); BMODE 1: B[k][n]=Bg[n*ldb+k]
//  EPI 0: +bias (opt relu); EPI 1: BN per-n + relu; EPI 2: BN per-m + relu
//  CVTA: convert A to tf32 on read (only needed when A is raw fp32)
//  ROUND: round stored C to tf32 (output feeds another GEMM)
// 3-stage cp.async pipeline, one __syncthreads per K-iter.
// Block: 256 thr (8 warps 2x4), tile 128x128x16, warp tile 64x32.
// ============================================================
template<int AMODE, int BMODE, int EPI, int CVTA, int ROUND>
__global__ void __launch_bounds__(256) gemm_tf32(
    const float* __restrict__ A, int lda, size_t sA,
    const float* __restrict__ Bg, int ldb, size_t sB,
    float* __restrict__ C, int ldc, size_t sC,
    const float* __restrict__ p0, const float* __restrict__ p1,
    const float* __restrict__ p2, const float* __restrict__ p3,
    int K, int relu)
{
    constexpr int AST = (AMODE == 0) ? 20 : 136;
    constexpr int ARS = (AMODE == 0) ? BM : BK;
    constexpr int ASZ = ARS * AST;       // floats per A stage
    constexpr int BSZ = BK * 136;        // floats per B stage
    extern __shared__ float smem[];
    float* As = smem;                    // 3 stages
    float* Bs = smem + 3 * ASZ;          // 3 stages

    int tid = threadIdx.x;
    int bm = blockIdx.x * BM, bn = blockIdx.y * BN;
    const float* Ab = A  + (size_t)blockIdx.z * sA;
    const float* Bb = Bg + (size_t)blockIdx.z * sB;
    float*       Cb = C  + (size_t)blockIdx.z * sC;

    float acc[4][4][4];
#pragma unroll
    for (int i = 0; i < 4; i++)
#pragma unroll
        for (int j = 0; j < 4; j++)
#pragma unroll
            for (int r = 0; r < 4; r++) acc[i][j][r] = 0.f;

    int lane = tid & 31, wid = tid >> 5;
    int wm = (wid >> 2) * 64, wn = (wid & 3) * 32;

    auto stage = [&](int s, int k0) {
        float* Asl = As + s * ASZ;
        float* Bsl = Bs + s * BSZ;
        if (AMODE == 0) {
#pragma unroll
            for (int id = tid; id < 512; id += 256) {
                int r = id >> 2, c4 = (id & 3) << 2;
                cp16(&Asl[r * AST + c4], Ab + (size_t)(bm + r) * lda + k0 + c4);
            }
        } else {
#pragma unroll
            for (int id = tid; id < 512; id += 256) {
                int k = id >> 5, m4 = (id & 31) << 2;
                cp16(&Asl[k * AST + m4], Ab + (size_t)(k0 + k) * lda + bm + m4);
            }
        }
        if (BMODE == 0) {
#pragma unroll
            for (int id = tid; id < 512; id += 256) {
                int k = id >> 5, n4 = (id & 31) << 2;
                cp16(&Bsl[k * 136 + n4], Bb + (size_t)(k0 + k) * ldb + bn + n4);
            }
            asm volatile("cp.async.commit_group;\n");
        } else {
            asm volatile("cp.async.commit_group;\n");
#pragma unroll
            for (int id = tid; id < 512; id += 256) {
                int n = id >> 2, kk = (id & 3) << 2;
                float4 v = *(const float4*)(Bb + (size_t)(bn + n) * ldb + k0 + kk);
                Bsl[(kk + 0) * 136 + n] = v.x;
                Bsl[(kk + 1) * 136 + n] = v.y;
                Bsl[(kk + 2) * 136 + n] = v.z;
                Bsl[(kk + 3) * 136 + n] = v.w;
            }
        }
    };

    stage(0, 0);
    stage(1, BK);

    int slot = 0;
    for (int k0 = 0; k0 < K; k0 += BK) {
        if (k0 + BK < K) asm volatile("cp.async.wait_group 1;\n");
        else             asm volatile("cp.async.wait_group 0;\n");
        __syncthreads();
        if (k0 + 2 * BK < K) {
            int ns = slot + 2; if (ns >= 3) ns -= 3;
            stage(ns, k0 + 2 * BK);
        }

        const float* Asl = As + slot * ASZ;
        const float* Bsl = Bs + slot * BSZ;
#pragma unroll
        for (int ks = 0; ks < 2; ks++) {
            uint32_t af[4][4], bf[4][2];
            int c0 = ks * 8 + (lane & 3);
            int rr = lane >> 2;
#pragma unroll
            for (int mt = 0; mt < 4; mt++) {
                int r0 = wm + mt * 16 + rr;
                float a0, a1, a2, a3;
                if (AMODE == 0) {
                    a0 = Asl[r0 * AST + c0];
                    a1 = Asl[(r0 + 8) * AST + c0];
                    a2 = Asl[r0 * AST + c0 + 4];
                    a3 = Asl[(r0 + 8) * AST + c0 + 4];
                } else {
                    a0 = Asl[c0 * AST + r0];
                    a1 = Asl[c0 * AST + r0 + 8];
                    a2 = Asl[(c0 + 4) * AST + r0];
                    a3 = Asl[(c0 + 4) * AST + r0 + 8];
                }
                if (CVTA) {
                    af[mt][0] = f2tf(a0); af[mt][1] = f2tf(a1);
                    af[mt][2] = f2tf(a2); af[mt][3] = f2tf(a3);
                } else {
                    af[mt][0] = __float_as_uint(a0); af[mt][1] = __float_as_uint(a1);
                    af[mt][2] = __float_as_uint(a2); af[mt][3] = __float_as_uint(a3);
                }
            }
#pragma unroll
            for (int nt = 0; nt < 4; nt++) {
                int nb = wn + nt * 8 + rr;
                bf[nt][0] = __float_as_uint(Bsl[c0 * 136 + nb]);
                bf[nt][1] = __float_as_uint(Bsl[(c0 + 4) * 136 + nb]);
            }
#pragma unroll
            for (int mt = 0; mt < 4; mt++)
#pragma unroll
                for (int nt = 0; nt < 4; nt++)
                    mma8(acc[mt][nt], af[mt], bf[nt]);
        }
        slot++; if (slot >= 3) slot -= 3;
    }

    // ---------------- epilogue ----------------
    int tig = lane & 3, grp = lane >> 2;
#pragma unroll
    for (int mt = 0; mt < 4; mt++) {
#pragma unroll
        for (int nt = 0; nt < 4; nt++) {
            int gm = bm + wm + mt * 16 + grp;
            int gn = bn + wn + nt * 8 + tig * 2;
            float* c = acc[mt][nt];
#pragma unroll
            for (int half = 0; half < 2; half++) {
                int row = gm + half * 8;
                float v0 = c[half * 2 + 0], v1 = c[half * 2 + 1];
                if (EPI == 0) {
                    v0 += p0[gn]; v1 += p0[gn + 1];
                    if (relu) { v0 = fmaxf(v0, 0.f); v1 = fmaxf(v1, 0.f); }
                } else if (EPI == 1) {
                    float s0 = rsqrtf(p3[gn] + EPS_) * p0[gn];
                    float s1 = rsqrtf(p3[gn + 1] + EPS_) * p0[gn + 1];
                    v0 = fmaxf((v0 - p2[gn]) * s0 + p1[gn], 0.f);
                    v1 = fmaxf((v1 - p2[gn + 1]) * s1 + p1[gn + 1], 0.f);
                } else {
                    float s = rsqrtf(p3[row] + EPS_) * p0[row];
                    float h = p1[row] - p2[row] * s;
                    v0 = fmaxf(v0 * s + h, 0.f);
                    v1 = fmaxf(v1 * s + h, 0.f);
                }
                if (ROUND) { v0 = f2tff(v0); v1 = f2tff(v1); }
                float2 o; o.x = v0; o.y = v1;
                *(float2*)&Cb[(size_t)row * ldc + gn] = o;
            }
        }
    }
}

// ============================================================
// round-copy: dst[i] = tf32(src[i])
// ============================================================
__global__ void round_copy_kernel(const float* __restrict__ src,
                                  float* __restrict__ dst, int n)
{
    int i = blockIdx.x * blockDim.x + threadIdx.x;
    if (i < n) dst[i] = f2tff(src[i]);
}

// ============================================================
// weight-prep: concat [Woff | Wattn | 0] -> wcat[L][D][128] (tf32 rounded)
// ============================================================
__global__ void prep_wcat_kernel(const float* __restrict__ Woff,
                                 const float* __restrict__ Wattn,
                                 float* __restrict__ wcat)
{
    int i = blockIdx.x * 256 + threadIdx.x;
    if (i >= L_ * D_ * 128) return;
    int l = i / (D_ * 128);
    int r = (i / 128) % D_;
    int c = i % 128;
    float v = 0.f;
    if (c < 64)      v = Woff[((size_t)l * D_ + r) * 64 + c];
    else if (c < 96) v = Wattn[((size_t)l * D_ + r) * 32 + (c - 64)];
    wcat[i] = f2tff(v);
}
__global__ void prep_bcat_kernel(const float* __restrict__ boff,
                                 const float* __restrict__ battn,
                                 float* __restrict__ bcat)
{
    int i = threadIdx.x + blockIdx.x * 256;
    if (i >= L_ * 128) return;
    int l = i / 128, c = i % 128;
    float v = 0.f;
    if (c < 64)      v = boff[l * 64 + c];
    else if (c < 96) v = battn[l * 32 + (c - 64)];
    bcat[i] = v;
}

// ============================================================
// q init: broadcast query_embed over batch (tf32-rounded, float4)
// ============================================================
__global__ void init_q_kernel(const float* __restrict__ qe, float* __restrict__ q)
{
    int i = blockIdx.x * blockDim.x + threadIdx.x;   // over HW_*D_/4
    if (i >= HW_ * D_ / 4) return;
    float4 v = ((const float4*)qe)[i];
    v.x = f2tff(v.x); v.y = f2tff(v.y); v.z = f2tff(v.z); v.w = f2tff(v.w);
#pragma unroll
    for (int b = 0; b < B_; b++)
        ((float4*)q)[(size_t)b * (HW_ * D_ / 4) + i] = v;
}

// ============================================================
// softmax over NP + sample-location compute from GEMM logits
// ============================================================
__global__ void __launch_bounds__(256) postproc_kernel(
    const float* __restrict__ lg, float* __restrict__ loc, float* __restrict__ attw)
{
    int row = blockIdx.x * 8 + (threadIdx.x >> 5);
    int t = threadIdx.x & 31;
    const float* p = lg + (size_t)row * 128;
    int h = t >> 2, pp = t & 3;
    float l0 = p[64 + h * 4 + 0], l1 = p[64 + h * 4 + 1];
    float l2 = p[64 + h * 4 + 2], l3 = p[64 + h * 4 + 3];
    float mx = fmaxf(fmaxf(l0, l1), fmaxf(l2, l3));
    float e0 = expf(l0 - mx), e1 = expf(l1 - mx), e2 = expf(l2 - mx), e3 = expf(l3 - mx);
    float s = e0 + e1 + e2 + e3;
    float my = (pp == 0) ? e0 : (pp == 1) ? e1 : (pp == 2) ? e2 : e3;
    attw[(size_t)row * 32 + t] = my / s;

    float offx = p[(h * 4 + pp) * 2 + 0];
    float offy = p[(h * 4 + pp) * 2 + 1];
    int hw = row & (HW_ - 1);
    float rx = ((hw & (WW_ - 1)) + 0.5f) * (1.f / WW_);
    float ry = ((hw >> 6) + 0.5f) * (1.f / HH_);
    loc[((size_t)row * 32 + t) * 2 + 0] = rx + offx * (1.f / WW_);
    loc[((size_t)row * 32 + t) * 2 + 1] = ry + offy * (1.f / HH_);
}

// ============================================================
// deformable bilinear sampling + attention-weighted sum
// warp per (query,head), lane = channel; output tf32-rounded (feeds Wo GEMM)
// ============================================================
__global__ void __launch_bounds__(256) sample_kernel(
    const float* __restrict__ val, const float* __restrict__ loc,
    const float* __restrict__ attw, float* __restrict__ out)
{
    int row = blockIdx.x;
    int b = row >> 12;
    int h = threadIdx.x >> 5;
    int lane = threadIdx.x & 31;

    const float* lp = loc  + ((size_t)row * 32 + h * NP_) * 2;
    const float* wp = attw + (size_t)row * 32 + h * NP_;
    float acc = 0.f;
#pragma unroll
    for (int p = 0; p < NP_; p++) {
        float lx = lp[p * 2 + 0], ly = lp[p * 2 + 1];
        float w = wp[p];
        float gx = lx * WW_ - 0.5f;
        float gy = ly * HH_ - 0.5f;
        float x0f = floorf(gx), y0f = floorf(gy);
        float wx = gx - x0f, wy = gy - y0f;
        int x0 = (int)x0f, y0 = (int)y0f;
        float v = 0.f;
#pragma unroll
        for (int dy = 0; dy < 2; dy++) {
#pragma unroll
            for (int dx = 0; dx < 2; dx++) {
                int xi = x0 + dx, yi = y0 + dy;
                if (xi >= 0 && xi < WW_ && yi >= 0 && yi < HH_) {
                    float cw = (dx ? wx : 1.f - wx) * (dy ? wy : 1.f - wy);
                    v += cw * val[((size_t)b * HW_ + yi * WW_ + xi) * D_ + h * 32 + lane];
                }
            }
        }
        acc += w * v;
    }
    out[(size_t)row * D_ + h * 32 + lane] = f2tff(acc);
}

// ============================================================
// q = LayerNorm(q + delta) * g + b ; block=256=D; output tf32-rounded
// ============================================================
__global__ void __launch_bounds__(256) add_ln_kernel(
    float* __restrict__ q, const float* __restrict__ delta,
    const float* __restrict__ g, const float* __restrict__ b)
{
    int row = blockIdx.x;
    int t = threadIdx.x;
    __shared__ float wsum[8];
    __shared__ float s_mean, s_var;
    size_t base = (size_t)row * D_;
    float v = q[base + t] + delta[base + t];

    float r = v;
#pragma unroll
    for (int o = 16; o > 0; o >>= 1) r += __shfl_xor_sync(0xffffffffu, r, o);
    if ((t & 31) == 0) wsum[t >> 5] = r;
    __syncthreads();
    if (t < 8) {
        float x = wsum[t];
#pragma unroll
        for (int o = 4; o > 0; o >>= 1) x += __shfl_xor_sync(0xffu, x, o);
        if (t == 0) s_mean = x * (1.f / D_);
    }
    __syncthreads();
    float d = v - s_mean;
    r = d * d;
#pragma unroll
    for (int o = 16; o > 0; o >>= 1) r += __shfl_xor_sync(0xffffffffu, r, o);
    if ((t & 31) == 0) wsum[t >> 5] = r;
    __syncthreads();
    if (t < 8) {
        float x = wsum[t];
#pragma unroll
        for (int o = 4; o > 0; o >>= 1) x += __shfl_xor_sync(0xffu, x, o);
        if (t == 0) s_var = x * (1.f / D_);
    }
    __syncthreads();
    q[base + t] = f2tff(d * rsqrtf(s_var + EPS_) * g[t] + b[t]);
}

// ============================================================
// host launcher
// ============================================================
extern "C" void kernel_launch(void* const* d_in, const int* in_sizes, int n_in,
                              void* d_out, int out_size)
{
    const float* x      = (const float*)d_in[0];
    const float* W_in   = (const float*)d_in[1];
    const float* bn1_g  = (const float*)d_in[2];
    const float* bn1_b  = (const float*)d_in[3];
    const float* bn1_m  = (const float*)d_in[4];
    const float* bn1_v  = (const float*)d_in[5];
    const float* qembed = (const float*)d_in[6];
    const float* Woff   = (const float*)d_in[7];
    const float* boff   = (const float*)d_in[8];
    const float* Wattn  = (const float*)d_in[9];
    const float* battn  = (const float*)d_in[10];
    const float* Wval   = (const float*)d_in[11];
    const float* bval   = (const float*)d_in[12];
    const float* Wo     = (const float*)d_in[13];
    const float* bo     = (const float*)d_in[14];
    const float* ln1_g  = (const float*)d_in[15];
    const float* ln1_b  = (const float*)d_in[16];
    const float* W1     = (const float*)d_in[17];
    const float* b1     = (const float*)d_in[18];
    const float* W2     = (const float*)d_in[19];
    const float* b2     = (const float*)d_in[20];
    const float* ln2_g  = (const float*)d_in[21];
    const float* ln2_b  = (const float*)d_in[22];
    const float* W_out  = (const float*)d_in[23];
    const float* bn2_g  = (const float*)d_in[24];
    const float* bn2_b  = (const float*)d_in[25];
    const float* bn2_m  = (const float*)d_in[26];
    const float* bn2_v  = (const float*)d_in[27];
    float* out = (float*)d_out;

    float *src, *q, *val, *samp, *tmp, *ffn, *loc, *attw, *logits, *wcat, *bcat, *rw;
    cudaGetSymbolAddress((void**)&src,    g_src);
    cudaGetSymbolAddress((void**)&q,      g_q);
    cudaGetSymbolAddress((void**)&val,    g_val);
    cudaGetSymbolAddress((void**)&samp,   g_samp);
    cudaGetSymbolAddress((void**)&tmp,    g_tmp);
    cudaGetSymbolAddress((void**)&ffn,    g_ffn);
    cudaGetSymbolAddress((void**)&loc,    g_loc);
    cudaGetSymbolAddress((void**)&attw,   g_attw);
    cudaGetSymbolAddress((void**)&logits, g_logits);
    cudaGetSymbolAddress((void**)&wcat,   g_wcat);
    cudaGetSymbolAddress((void**)&bcat,   g_bcat);
    cudaGetSymbolAddress((void**)&rw,     g_rw);

    const int M = B_ * HW_;  // 32768
    dim3 blk(256);

    // dynamic smem sizes per instantiation
    const int SM_A0 = 3 * (BM * 20 + BK * 136) * 4;   // 56832
    const int SM_A1 = 3 * (BK * 136 + BK * 136) * 4;  // 52224
    cudaFuncSetAttribute(gemm_tf32<0,0,0,0,0>, cudaFuncAttributeMaxDynamicSharedMemorySize, SM_A0);
    cudaFuncSetAttribute(gemm_tf32<0,0,0,0,1>, cudaFuncAttributeMaxDynamicSharedMemorySize, SM_A0);
    cudaFuncSetAttribute(gemm_tf32<1,1,1,1,1>, cudaFuncAttributeMaxDynamicSharedMemorySize, SM_A1);
    cudaFuncSetAttribute(gemm_tf32<0,1,2,0,0>, cudaFuncAttributeMaxDynamicSharedMemorySize, SM_A0);

    // ---- weight prep (tf32 pre-rounding) ----
    round_copy_kernel<<<(131072 + 255) / 256, 256>>>(W_in,  rw + OW_IN,  131072);
    round_copy_kernel<<<(131072 + 255) / 256, 256>>>(Wval,  rw + OW_VAL, 131072);
    round_copy_kernel<<<(131072 + 255) / 256, 256>>>(Wo,    rw + OW_O,   131072);
    round_copy_kernel<<<(524288 + 255) / 256, 256>>>(W1,    rw + OW_1,   524288);
    round_copy_kernel<<<(524288 + 255) / 256, 256>>>(W2,    rw + OW_2,   524288);
    round_copy_kernel<<<(131072 + 255) / 256, 256>>>(W_out, rw + OW_OUT, 131072);
    prep_wcat_kernel<<<(L_ * D_ * 128 + 255) / 256, 256>>>(Woff, Wattn, wcat);
    prep_bcat_kernel<<<1, 256>>>(boff, battn, bcat);

    // proj_in: A = x (raw, CVTA=1), B = W_in cols (pre-rounded), BN per-n, ROUND
    gemm_tf32<1, 1, 1, 1, 1><<<dim3(HW_ / BM, D_ / BN, B_), blk, SM_A1>>>(
        x, HW_, (size_t)CIN_ * HW_,
        rw + OW_IN, CIN_, 0,
        src, D_, (size_t)HW_ * D_,
        bn1_g, bn1_b, bn1_m, bn1_v, CIN_, 0);

    init_q_kernel<<<(HW_ * D_ / 4 + 255) / 256, 256>>>(qembed, q);

    for (int l = 0; l < L_; l++) {
        gemm_tf32<0, 0, 0, 0, 0><<<dim3(M / BM, D_ / BN, 1), blk, SM_A0>>>(
            src, D_, 0, rw + OW_VAL + (size_t)l * D_ * D_, D_, 0,
            val, D_, 0, bval + l * D_, nullptr, nullptr, nullptr, D_, 0);

        gemm_tf32<0, 0, 0, 0, 0><<<dim3(M / BM, 1, 1), blk, SM_A0>>>(
            q, D_, 0, wcat + (size_t)l * D_ * 128, 128, 0,
            logits, 128, 0, bcat + l * 128, nullptr, nullptr, nullptr, D_, 0);

        postproc_kernel<<<M / 8, 256>>>(logits, loc, attw);

        sample_kernel<<<M, 256>>>(val, loc, attw, samp);

        gemm_tf32<0, 0, 0, 0, 0><<<dim3(M / BM, D_ / BN, 1), blk, SM_A0>>>(
            samp, D_, 0, rw + OW_O + (size_t)l * D_ * D_, D_, 0,
            tmp, D_, 0, bo + l * D_, nullptr, nullptr, nullptr, D_, 0);

        add_ln_kernel<<<M, D_>>>(q, tmp, ln1_g + l * D_, ln1_b + l * D_);

        gemm_tf32<0, 0, 0, 0, 1><<<dim3(M / BM, DFF_ / BN, 1), blk, SM_A0>>>(
            q, D_, 0, rw + OW_1 + (size_t)l * D_ * DFF_, DFF_, 0,
            ffn, DFF_, 0, b1 + l * DFF_, nullptr, nullptr, nullptr, D_, 1);

        gemm_tf32<0, 0, 0, 0, 0><<<dim3(M / BM, D_ / BN, 1), blk, SM_A0>>>(
            ffn, DFF_, 0, rw + OW_2 + (size_t)l * DFF_ * D_, D_, 0,
            tmp, D_, 0, b2 + l * D_, nullptr, nullptr, nullptr, DFF_, 0);

        add_ln_kernel<<<M, D_>>>(q, tmp, ln2_g + l * D_, ln2_b + l * D_);
    }

    // proj_out: A = W_out (pre-rounded), B = q cols (pre-rounded), BN per-m
    gemm_tf32<0, 1, 2, 0, 0><<<dim3(CIN_ / BM, HW_ / BN, B_), blk, SM_A0>>>(
        rw + OW_OUT, D_, 0,
        q, D_, (size_t)HW_ * D_,
        out, HW_, (size_t)CIN_ * HW_,
        bn2_g, bn2_b, bn2_m, bn2_v, D_, 0);
}

// round 11
// speedup vs baseline: 1.3865x; 1.3865x over previous
#include <cuda_runtime.h>
#include <cuda_fp16.h>
#include <math.h>
#include <stdint.h>

// ---------------- problem constants ----------------
#define L_    2
#define D_    256
#define DFF_  1024
#define NH_   8
#define NP_   4
#define CIN_  512
#define B_    8
#define HH_   64
#define WW_   64
#define HW_   4096
#define EPS_  1e-5f

// ---------------- GEMM tiling ----------------
#define BM 128
#define BN 128
#define BK 32
#define ASTR 40           // halfs per smem row (32 data + 8 pad) -> conflict-free
#define STAGE_H (BM * ASTR)   // halfs per A (or B) stage = 5120

// ---------------- scratch (device globals; allocation-free) ----------------
__device__ __align__(128) float  g_q     [B_*HW_*D_];     // fp32 residual master
__device__ __align__(128) float  g_tmp   [B_*HW_*D_];     // fp32 GEMM out for LN
__device__ __align__(128) float  g_logits[B_*HW_*128];
__device__ __align__(128) float  g_loc   [B_*HW_*NH_*NP_*2];
__device__ __align__(128) float  g_attw  [B_*HW_*NH_*NP_];
__device__ __align__(128) float  g_bcat  [L_*128];

__device__ __align__(128) __half h_x    [B_*HW_*CIN_];    // x transposed [b][hw][c]
__device__ __align__(128) __half h_src  [B_*HW_*D_];
__device__ __align__(128) __half h_q    [B_*HW_*D_];
__device__ __align__(128) __half h_val  [B_*HW_*D_];
__device__ __align__(128) __half h_samp [B_*HW_*D_];
__device__ __align__(128) __half h_ffn  [B_*HW_*DFF_];

__device__ __align__(128) __half h_Win  [D_*CIN_];        // [D][CIN] (already N-major)
__device__ __align__(128) __half h_Wout [CIN_*D_];        // [CIN][D] (A-side, row-major)
__device__ __align__(128) __half h_WvalT[L_*D_*D_];       // [n][k]
__device__ __align__(128) __half h_WoT  [L_*D_*D_];
__device__ __align__(128) __half h_W1T  [L_*DFF_*D_];     // [DFF][D]
__device__ __align__(128) __half h_W2T  [L_*D_*DFF_];     // [D][DFF]
__device__ __align__(128) __half h_wcatT[L_*128*D_];      // [128][D]

// ---------------- helpers ----------------
__device__ __forceinline__ void cp16(void* dst, const void* src) {
    uint32_t d = (uint32_t)__cvta_generic_to_shared(dst);
    asm volatile("cp.async.cg.shared.global [%0], [%1], 16;\n" :: "r"(d), "l"(src));
}
__device__ __forceinline__ void mma16(float* c, const uint32_t* a, const uint32_t* b) {
    asm volatile(
        "mma.sync.aligned.m16n8k16.row.col.f32.f16.f16.f32 "
        "{%0,%1,%2,%3},{%4,%5,%6,%7},{%8,%9},{%0,%1,%2,%3};"
        : "+f"(c[0]), "+f"(c[1]), "+f"(c[2]), "+f"(c[3])
        : "r"(a[0]), "r"(a[1]), "r"(a[2]), "r"(a[3]), "r"(b[0]), "r"(b[1]));
}

// ============================================================
// fp16 tensor-core GEMM. C[M,N] = A[M,K] @ B^T + epilogue
//  A: fp16 row-major [M][K] (lda); B: fp16 [N][K] (ldb) -> .col operand
//  EPI 0: +bias(optional relu); 1: BN per-n + relu; 2: BN per-m + relu
//  OUTH 1: store fp16; 0: store fp32
// 3-stage cp.async, tile 128x128x32, 8 warps (2x4), warp tile 64x32.
// ============================================================
template<int EPI, int OUTH>
__global__ void __launch_bounds__(256) gemm_h(
    const __half* __restrict__ A, int lda, size_t sA,
    const __half* __restrict__ Bh, int ldb, size_t sB,
    void* __restrict__ C, int ldc, size_t sC,
    const float* __restrict__ p0, const float* __restrict__ p1,
    const float* __restrict__ p2, const float* __restrict__ p3,
    int K, int relu)
{
    extern __shared__ __half smem[];
    __half* As = smem;                       // 3 stages of STAGE_H
    __half* Bs = smem + 3 * STAGE_H;

    int tid = threadIdx.x;
    int bm = blockIdx.x * BM, bn = blockIdx.y * BN;
    const __half* Ab = A  + (size_t)blockIdx.z * sA;
    const __half* Bb = Bh + (size_t)blockIdx.z * sB;

    float acc[4][4][4];
#pragma unroll
    for (int i = 0; i < 4; i++)
#pragma unroll
        for (int j = 0; j < 4; j++)
#pragma unroll
            for (int r = 0; r < 4; r++) acc[i][j][r] = 0.f;

    int lane = tid & 31, wid = tid >> 5;
    int wm = (wid >> 2) * 64, wn = (wid & 3) * 32;
    int grp = lane >> 2, tig = lane & 3;

    auto stage = [&](int s, int k0) {
        __half* Asl = As + s * STAGE_H;
        __half* Bsl = Bs + s * STAGE_H;
#pragma unroll
        for (int id = tid; id < 512; id += 256) {
            int r = id >> 2, kc = (id & 3) << 3;
            cp16(&Asl[r * ASTR + kc], Ab + (size_t)(bm + r) * lda + k0 + kc);
        }
#pragma unroll
        for (int id = tid; id < 512; id += 256) {
            int r = id >> 2, kc = (id & 3) << 3;
            cp16(&Bsl[r * ASTR + kc], Bb + (size_t)(bn + r) * ldb + k0 + kc);
        }
        asm volatile("cp.async.commit_group;\n");
    };

    stage(0, 0);
    stage(1, BK);

    int slot = 0;
    for (int k0 = 0; k0 < K; k0 += BK) {
        if (k0 + BK < K) asm volatile("cp.async.wait_group 1;\n");
        else             asm volatile("cp.async.wait_group 0;\n");
        __syncthreads();
        if (k0 + 2 * BK < K) {
            int ns = slot + 2; if (ns >= 3) ns -= 3;
            stage(ns, k0 + 2 * BK);
        }

        const uint32_t* Aw = (const uint32_t*)(As + slot * STAGE_H);
        const uint32_t* Bw = (const uint32_t*)(Bs + slot * STAGE_H);
#pragma unroll
        for (int ks = 0; ks < 2; ks++) {
            uint32_t af[4][4], bf[4][2];
            int kb = ks * 8 + tig;                 // word offset within row
#pragma unroll
            for (int mt = 0; mt < 4; mt++) {
                int r0 = wm + mt * 16 + grp;
                int base = r0 * (ASTR / 2) + kb;
                af[mt][0] = Aw[base];
                af[mt][1] = Aw[base + 8 * (ASTR / 2)];
                af[mt][2] = Aw[base + 4];
                af[mt][3] = Aw[base + 8 * (ASTR / 2) + 4];
            }
#pragma unroll
            for (int nt = 0; nt < 4; nt++) {
                int n0 = wn + nt * 8 + grp;
                int base = n0 * (ASTR / 2) + kb;
                bf[nt][0] = Bw[base];
                bf[nt][1] = Bw[base + 4];
            }
#pragma unroll
            for (int mt = 0; mt < 4; mt++)
#pragma unroll
                for (int nt = 0; nt < 4; nt++)
                    mma16(acc[mt][nt], af[mt], bf[nt]);
        }
        slot++; if (slot >= 3) slot -= 3;
    }

    // ---------------- epilogue ----------------
#pragma unroll
    for (int mt = 0; mt < 4; mt++) {
#pragma unroll
        for (int nt = 0; nt < 4; nt++) {
            int gm = bm + wm + mt * 16 + grp;
            int gn = bn + wn + nt * 8 + tig * 2;
            float* c = acc[mt][nt];
#pragma unroll
            for (int half = 0; half < 2; half++) {
                int row = gm + half * 8;
                float v0 = c[half * 2 + 0], v1 = c[half * 2 + 1];
                if (EPI == 0) {
                    v0 += p0[gn]; v1 += p0[gn + 1];
                    if (relu) { v0 = fmaxf(v0, 0.f); v1 = fmaxf(v1, 0.f); }
                } else if (EPI == 1) {
                    float s0 = rsqrtf(p3[gn] + EPS_) * p0[gn];
                    float s1 = rsqrtf(p3[gn + 1] + EPS_) * p0[gn + 1];
                    v0 = fmaxf((v0 - p2[gn]) * s0 + p1[gn], 0.f);
                    v1 = fmaxf((v1 - p2[gn + 1]) * s1 + p1[gn + 1], 0.f);
                } else {
                    float s = rsqrtf(p3[row] + EPS_) * p0[row];
                    float h = p1[row] - p2[row] * s;
                    v0 = fmaxf(v0 * s + h, 0.f);
                    v1 = fmaxf(v1 * s + h, 0.f);
                }
                size_t off = (size_t)((size_t)blockIdx.z * sC) + (size_t)row * ldc + gn;
                if (OUTH) {
                    __half2 hv = __floats2half2_rn(v0, v1);
                    *(__half2*)((__half*)C + off) = hv;
                } else {
                    float2 o; o.x = v0; o.y = v1;
                    *(float2*)((float*)C + off) = o;
                }
            }
        }
    }
}

// ============================================================
// prep: fp32 -> fp16 convert (same layout)
// ============================================================
__global__ void cvt_h_kernel(const float* __restrict__ src, __half* __restrict__ dst, int n)
{
    int i = blockIdx.x * blockDim.x + threadIdx.x;
    if (i < n) dst[i] = __float2half(src[i]);
}

// ============================================================
// prep: transpose + convert  src fp32 [R][C] -> dst fp16 [C][R], batched
// block 32x8, tile 32x32
// ============================================================
__global__ void transpose_h_kernel(const float* __restrict__ src, __half* __restrict__ dst,
                                   int R, int C, size_t ssrc, size_t sdst)
{
    __shared__ float t[32][33];
    const float* s = src + (size_t)blockIdx.z * ssrc;
    __half* d = dst + (size_t)blockIdx.z * sdst;
    int r0 = blockIdx.y * 32, c0 = blockIdx.x * 32;
    int tx = threadIdx.x, ty = threadIdx.y;
#pragma unroll
    for (int i = 0; i < 32; i += 8)
        t[ty + i][tx] = s[(size_t)(r0 + ty + i) * C + c0 + tx];
    __syncthreads();
#pragma unroll
    for (int i = 0; i < 32; i += 8)
        d[(size_t)(c0 + ty + i) * R + r0 + tx] = __float2half(t[tx][ty + i]);
}

// ============================================================
// prep: wcatT[l][c][d] = c<64 ? Woff[l][d][c] : c<96 ? Wattn[l][d][c-64] : 0
// ============================================================
__global__ void prep_wcat_kernel(const float* __restrict__ Woff,
                                 const float* __restrict__ Wattn,
                                 __half* __restrict__ wcatT)
{
    int i = blockIdx.x * 256 + threadIdx.x;
    if (i >= L_ * 128 * D_) return;
    int l = i / (128 * D_);
    int c = (i / D_) % 128;
    int d = i % D_;
    float v = 0.f;
    if (c < 64)      v = Woff[((size_t)l * D_ + d) * 64 + c];
    else if (c < 96) v = Wattn[((size_t)l * D_ + d) * 32 + (c - 64)];
    wcatT[i] = __float2half(v);
}
__global__ void prep_bcat_kernel(const float* __restrict__ boff,
                                 const float* __restrict__ battn,
                                 float* __restrict__ bcat)
{
    int i = threadIdx.x + blockIdx.x * 256;
    if (i >= L_ * 128) return;
    int l = i / 128, c = i % 128;
    float v = 0.f;
    if (c < 64)      v = boff[l * 64 + c];
    else if (c < 96) v = battn[l * 32 + (c - 64)];
    bcat[i] = v;
}

// ============================================================
// q init: broadcast query_embed over batch; fp32 master + fp16 copy
// ============================================================
__global__ void init_q_kernel(const float* __restrict__ qe,
                              float* __restrict__ q, __half* __restrict__ qh)
{
    int i = blockIdx.x * blockDim.x + threadIdx.x;   // over HW_*D_/4
    if (i >= HW_ * D_ / 4) return;
    float4 v = ((const float4*)qe)[i];
    __half2 h0 = __floats2half2_rn(v.x, v.y);
    __half2 h1 = __floats2half2_rn(v.z, v.w);
#pragma unroll
    for (int b = 0; b < B_; b++) {
        ((float4*)q)[(size_t)b * (HW_ * D_ / 4) + i] = v;
        ((__half2*)qh)[((size_t)b * (HW_ * D_ / 4) + i) * 2 + 0] = h0;
        ((__half2*)qh)[((size_t)b * (HW_ * D_ / 4) + i) * 2 + 1] = h1;
    }
}

// ============================================================
// softmax over NP + sample-location compute from GEMM logits
// ============================================================
__global__ void __launch_bounds__(256) postproc_kernel(
    const float* __restrict__ lg, float* __restrict__ loc, float* __restrict__ attw)
{
    int row = blockIdx.x * 8 + (threadIdx.x >> 5);
    int t = threadIdx.x & 31;
    const float* p = lg + (size_t)row * 128;
    int h = t >> 2, pp = t & 3;
    float l0 = p[64 + h * 4 + 0], l1 = p[64 + h * 4 + 1];
    float l2 = p[64 + h * 4 + 2], l3 = p[64 + h * 4 + 3];
    float mx = fmaxf(fmaxf(l0, l1), fmaxf(l2, l3));
    float e0 = expf(l0 - mx), e1 = expf(l1 - mx), e2 = expf(l2 - mx), e3 = expf(l3 - mx);
    float s = e0 + e1 + e2 + e3;
    float my = (pp == 0) ? e0 : (pp == 1) ? e1 : (pp == 2) ? e2 : e3;
    attw[(size_t)row * 32 + t] = my / s;

    float offx = p[(h * 4 + pp) * 2 + 0];
    float offy = p[(h * 4 + pp) * 2 + 1];
    int hw = row & (HW_ - 1);
    float rx = ((hw & (WW_ - 1)) + 0.5f) * (1.f / WW_);
    float ry = ((hw >> 6) + 0.5f) * (1.f / HH_);
    loc[((size_t)row * 32 + t) * 2 + 0] = rx + offx * (1.f / WW_);
    loc[((size_t)row * 32 + t) * 2 + 1] = ry + offy * (1.f / HH_);
}

// ============================================================
// deformable bilinear sampling (fp16 val) + weighted sum -> fp16 samp
// warp per (query,head), lane = channel within head (dh=32)
// ============================================================
__global__ void __launch_bounds__(256) sample_kernel(
    const __half* __restrict__ val, const float* __restrict__ loc,
    const float* __restrict__ attw, __half* __restrict__ out)
{
    int row = blockIdx.x;
    int b = row >> 12;
    int h = threadIdx.x >> 5;
    int lane = threadIdx.x & 31;

    const float* lp = loc  + ((size_t)row * 32 + h * NP_) * 2;
    const float* wp = attw + (size_t)row * 32 + h * NP_;
    float acc = 0.f;
#pragma unroll
    for (int p = 0; p < NP_; p++) {
        float lx = lp[p * 2 + 0], ly = lp[p * 2 + 1];
        float w = wp[p];
        float gx = lx * WW_ - 0.5f;
        float gy = ly * HH_ - 0.5f;
        float x0f = floorf(gx), y0f = floorf(gy);
        float wx = gx - x0f, wy = gy - y0f;
        int x0 = (int)x0f, y0 = (int)y0f;
        float v = 0.f;
#pragma unroll
        for (int dy = 0; dy < 2; dy++) {
#pragma unroll
            for (int dx = 0; dx < 2; dx++) {
                int xi = x0 + dx, yi = y0 + dy;
                if (xi >= 0 && xi < WW_ && yi >= 0 && yi < HH_) {
                    float cw = (dx ? wx : 1.f - wx) * (dy ? wy : 1.f - wy);
                    v += cw * __half2float(val[((size_t)b * HW_ + yi * WW_ + xi) * D_ + h * 32 + lane]);
                }
            }
        }
        acc += w * v;
    }
    out[(size_t)row * D_ + h * 32 + lane] = __float2half(acc);
}

// ============================================================
// q = LayerNorm(q + delta)*g + b; fp32 master + fp16 copy for GEMMs
// ============================================================
__global__ void __launch_bounds__(256) add_ln_kernel(
    float* __restrict__ q, const float* __restrict__ delta,
    const float* __restrict__ g, const float* __restrict__ b,
    __half* __restrict__ qh)
{
    int row = blockIdx.x;
    int t = threadIdx.x;
    __shared__ float wsum[8];
    __shared__ float s_mean, s_var;
    size_t base = (size_t)row * D_;
    float v = q[base + t] + delta[base + t];

    float r = v;
#pragma unroll
    for (int o = 16; o > 0; o >>= 1) r += __shfl_xor_sync(0xffffffffu, r, o);
    if ((t & 31) == 0) wsum[t >> 5] = r;
    __syncthreads();
    if (t < 8) {
        float x = wsum[t];
#pragma unroll
        for (int o = 4; o > 0; o >>= 1) x += __shfl_xor_sync(0xffu, x, o);
        if (t == 0) s_mean = x * (1.f / D_);
    }
    __syncthreads();
    float d = v - s_mean;
    r = d * d;
#pragma unroll
    for (int o = 16; o > 0; o >>= 1) r += __shfl_xor_sync(0xffffffffu, r, o);
    if ((t & 31) == 0) wsum[t >> 5] = r;
    __syncthreads();
    if (t < 8) {
        float x = wsum[t];
#pragma unroll
        for (int o = 4; o > 0; o >>= 1) x += __shfl_xor_sync(0xffu, x, o);
        if (t == 0) s_var = x * (1.f / D_);
    }
    __syncthreads();
    float o = d * rsqrtf(s_var + EPS_) * g[t] + b[t];
    q[base + t] = o;
    qh[base + t] = __float2half(o);
}

// ============================================================
// host launcher
// ============================================================
extern "C" void kernel_launch(void* const* d_in, const int* in_sizes, int n_in,
                              void* d_out, int out_size)
{
    const float* x      = (const float*)d_in[0];
    const float* W_in   = (const float*)d_in[1];
    const float* bn1_g  = (const float*)d_in[2];
    const float* bn1_b  = (const float*)d_in[3];
    const float* bn1_m  = (const float*)d_in[4];
    const float* bn1_v  = (const float*)d_in[5];
    const float* qembed = (const float*)d_in[6];
    const float* Woff   = (const float*)d_in[7];
    const float* boff   = (const float*)d_in[8];
    const float* Wattn  = (const float*)d_in[9];
    const float* battn  = (const float*)d_in[10];
    const float* Wval   = (const float*)d_in[11];
    const float* bval   = (const float*)d_in[12];
    const float* Wo     = (const float*)d_in[13];
    const float* bo     = (const float*)d_in[14];
    const float* ln1_g  = (const float*)d_in[15];
    const float* ln1_b  = (const float*)d_in[16];
    const float* W1     = (const float*)d_in[17];
    const float* b1     = (const float*)d_in[18];
    const float* W2     = (const float*)d_in[19];
    const float* b2     = (const float*)d_in[20];
    const float* ln2_g  = (const float*)d_in[21];
    const float* ln2_b  = (const float*)d_in[22];
    const float* W_out  = (const float*)d_in[23];
    const float* bn2_g  = (const float*)d_in[24];
    const float* bn2_b  = (const float*)d_in[25];
    const float* bn2_m  = (const float*)d_in[26];
    const float* bn2_v  = (const float*)d_in[27];
    float* out = (float*)d_out;

    float *q, *tmp, *logits, *loc, *attw, *bcat;
    __half *xh, *srch, *qh, *valh, *samph, *ffnh;
    __half *Winh, *Wouth, *WvalT, *WoT, *W1T, *W2T, *wcatT;
    cudaGetSymbolAddress((void**)&q,      g_q);
    cudaGetSymbolAddress((void**)&tmp,    g_tmp);
    cudaGetSymbolAddress((void**)&logits, g_logits);
    cudaGetSymbolAddress((void**)&loc,    g_loc);
    cudaGetSymbolAddress((void**)&attw,   g_attw);
    cudaGetSymbolAddress((void**)&bcat,   g_bcat);
    cudaGetSymbolAddress((void**)&xh,     h_x);
    cudaGetSymbolAddress((void**)&srch,   h_src);
    cudaGetSymbolAddress((void**)&qh,     h_q);
    cudaGetSymbolAddress((void**)&valh,   h_val);
    cudaGetSymbolAddress((void**)&samph,  h_samp);
    cudaGetSymbolAddress((void**)&ffnh,   h_ffn);
    cudaGetSymbolAddress((void**)&Winh,   h_Win);
    cudaGetSymbolAddress((void**)&Wouth,  h_Wout);
    cudaGetSymbolAddress((void**)&WvalT,  h_WvalT);
    cudaGetSymbolAddress((void**)&WoT,    h_WoT);
    cudaGetSymbolAddress((void**)&W1T,    h_W1T);
    cudaGetSymbolAddress((void**)&W2T,    h_W2T);
    cudaGetSymbolAddress((void**)&wcatT,  h_wcatT);

    const int M = B_ * HW_;  // 32768
    dim3 blk(256);
    dim3 tblk(32, 8);
    const int SMEM = 6 * STAGE_H * 2;  // 61440 bytes

    cudaFuncSetAttribute(gemm_h<0,0>, cudaFuncAttributeMaxDynamicSharedMemorySize, SMEM);
    cudaFuncSetAttribute(gemm_h<0,1>, cudaFuncAttributeMaxDynamicSharedMemorySize, SMEM);
    cudaFuncSetAttribute(gemm_h<1,1>, cudaFuncAttributeMaxDynamicSharedMemorySize, SMEM);
    cudaFuncSetAttribute(gemm_h<2,0>, cudaFuncAttributeMaxDynamicSharedMemorySize, SMEM);

    // ---- prep: weight conversion / transposition ----
    cvt_h_kernel<<<(D_*CIN_ + 255)/256, 256>>>(W_in,  Winh,  D_*CIN_);
    cvt_h_kernel<<<(CIN_*D_ + 255)/256, 256>>>(W_out, Wouth, CIN_*D_);
    transpose_h_kernel<<<dim3(D_/32, D_/32, L_), tblk>>>(Wval, WvalT, D_, D_, (size_t)D_*D_, (size_t)D_*D_);
    transpose_h_kernel<<<dim3(DFF_/32, D_/32, L_), tblk>>>(W1, W1T, D_, DFF_, (size_t)D_*DFF_, (size_t)D_*DFF_);
    transpose_h_kernel<<<dim3(D_/32, DFF_/32, L_), tblk>>>(W2, W2T, DFF_, D_, (size_t)DFF_*D_, (size_t)DFF_*D_);
    transpose_h_kernel<<<dim3(D_/32, D_/32, L_), tblk>>>(Wo, WoT, D_, D_, (size_t)D_*D_, (size_t)D_*D_);
    transpose_h_kernel<<<dim3(HW_/32, CIN_/32, B_), tblk>>>(x, xh, CIN_, HW_, (size_t)CIN_*HW_, (size_t)CIN_*HW_);
    prep_wcat_kernel<<<(L_*128*D_ + 255)/256, 256>>>(Woff, Wattn, wcatT);
    prep_bcat_kernel<<<1, 256>>>(boff, battn, bcat);

    // proj_in: A = xh[b] (HW x CIN), B = Winh (D x CIN), BN per-n + relu -> src fp16
    gemm_h<1, 1><<<dim3(HW_/BM, D_/BN, B_), blk, SMEM>>>(
        xh, CIN_, (size_t)HW_*CIN_,
        Winh, CIN_, 0,
        srch, D_, (size_t)HW_*D_,
        bn1_g, bn1_b, bn1_m, bn1_v, CIN_, 0);

    init_q_kernel<<<(HW_*D_/4 + 255)/256, 256>>>(qembed, q, qh);

    for (int l = 0; l < L_; l++) {
        gemm_h<0, 1><<<dim3(M/BM, D_/BN, 1), blk, SMEM>>>(
            srch, D_, 0, WvalT + (size_t)l*D_*D_, D_, 0,
            valh, D_, 0, bval + l*D_, nullptr, nullptr, nullptr, D_, 0);

        gemm_h<0, 0><<<dim3(M/BM, 1, 1), blk, SMEM>>>(
            qh, D_, 0, wcatT + (size_t)l*128*D_, D_, 0,
            logits, 128, 0, bcat + l*128, nullptr, nullptr, nullptr, D_, 0);

        postproc_kernel<<<M/8, 256>>>(logits, loc, attw);

        sample_kernel<<<M, 256>>>(valh, loc, attw, samph);

        gemm_h<0, 0><<<dim3(M/BM, D_/BN, 1), blk, SMEM>>>(
            samph, D_, 0, WoT + (size_t)l*D_*D_, D_, 0,
            tmp, D_, 0, bo + l*D_, nullptr, nullptr, nullptr, D_, 0);

        add_ln_kernel<<<M, D_>>>(q, tmp, ln1_g + l*D_, ln1_b + l*D_, qh);

        gemm_h<0, 1><<<dim3(M/BM, DFF_/BN, 1), blk, SMEM>>>(
            qh, D_, 0, W1T + (size_t)l*DFF_*D_, D_, 0,
            ffnh, DFF_, 0, b1 + l*DFF_, nullptr, nullptr, nullptr, D_, 1);

        gemm_h<0, 0><<<dim3(M/BM, D_/BN, 1), blk, SMEM>>>(
            ffnh, DFF_, 0, W2T + (size_t)l*D_*DFF_, DFF_, 0,
            tmp, D_, 0, b2 + l*D_, nullptr, nullptr, nullptr, DFF_, 0);

        add_ln_kernel<<<M, D_>>>(q, tmp, ln2_g + l*D_, ln2_b + l*D_, qh);
    }

    // proj_out: A = Wouth (CIN x D), B = qh[b] (HW x D), BN per-m + relu -> out fp32
    gemm_h<2, 0><<<dim3(CIN_/BM, HW_/BN, B_), blk, SMEM>>>(
        Wouth, D_, 0,
        qh, D_, (size_t)HW_*D_,
        out, HW_, (size_t)CIN_*HW_,
        bn2_g, bn2_b, bn2_m, bn2_v, D_, 0);
}